// round 3
// baseline (speedup 1.0000x reference)
#include <cuda_runtime.h>
#include <math.h>

// BiLSTM: B=128, S=1024, D=128, H=256.
// Grid: 128 CTAs = dir(2) x btile(4, 32 batches) x hslice(16, 16 h).
// CTA: 64 rows (4 gates x 16 h) x 32 batches, K=384, 256 threads.
// f32x2 packed FFMA; x/h smem tiles stored duplicated so LDS.128 yields
// ready f32x2 operand pairs. GEMM split: Wh*h (K=256) on the critical path,
// Wx*x_t (K=128) computed after the barrier signal to hide exchange latency.

#define S_LEN   1024
#define B_DIM   128
#define D_DIM   128
#define H_DIM   256
#define KCAT    384
#define NTHR    256

// smem layout (floats)
#define W_OFF   0          // w_s[384][64]   rows r = g*16+hh
#define X_OFF   24576      // x_s[128][64]   duplicated cols
#define H_OFF   32768      // h_s[256][64]   duplicated cols
#define Z_OFF   49152      // z_s[64][32]
#define C_OFF   51200      // c_s[16][32]
#define SMEM_FLOATS 51712
#define SMEM_BYTES  (SMEM_FLOATS * 4)

typedef unsigned long long u64;

__device__ float g_hT[2][2][H_DIM][B_DIM];   // [parity][dir][k][b] transposed
__device__ unsigned int g_bar[8];

__global__ void reset_bar_kernel() {
    if (threadIdx.x < 8) g_bar[threadIdx.x] = 0u;
}

__device__ __forceinline__ u64 ffma2(u64 a, u64 b, u64 c) {
    u64 d;
    asm("fma.rn.f32x2 %0, %1, %2, %3;" : "=l"(d) : "l"(a), "l"(b), "l"(c));
    return d;
}
__device__ __forceinline__ u64 pack2(float lo, float hi) {
    u64 d;
    asm("mov.b64 %0, {%1, %2};" : "=l"(d) : "f"(lo), "f"(hi));
    return d;
}
__device__ __forceinline__ void unpack2(u64 v, float& lo, float& hi) {
    asm("mov.b64 {%0, %1}, %2;" : "=f"(lo), "=f"(hi) : "l"(v));
}

__device__ __forceinline__ float sigmoidf_fast(float x) {
    return 1.0f / (1.0f + __expf(-x));
}
__device__ __forceinline__ float tanhf_fast(float x) {
    return 1.0f - 2.0f / (1.0f + __expf(2.0f * x));
}

__global__ void __launch_bounds__(NTHR, 1)
bilstm_kernel(const float* __restrict__ x,
              const float* __restrict__ Wf, const float* __restrict__ bf,
              const float* __restrict__ Wb, const float* __restrict__ bb,
              float* __restrict__ out)
{
    extern __shared__ float smem[];
    float* w_s = smem + W_OFF;
    float* x_s = smem + X_OFF;
    float* h_s = smem + H_OFF;
    float* z_s = smem + Z_OFF;
    float* c_s = smem + C_OFF;

    const int tid = threadIdx.x;
    const int cta = blockIdx.x;          // 0..127
    const int dir = cta >> 6;
    const int bt  = (cta >> 4) & 3;
    const int ht  = cta & 15;
    const int grp = cta >> 4;            // 0..7

    const float* W   = dir ? Wb : Wf;    // (4,256,384)
    const float* bia = dir ? bb : bf;    // (4,256)
    const int b_base = bt * 32;

    // ---- weights: w_s[k][r], r = g*16+hh, h = ht*16+hh ----
    for (int idx = tid; idx < KCAT * 64; idx += NTHR) {
        int k = idx % KCAT;
        int r = idx / KCAT;
        int g = r >> 4, hh = r & 15;
        w_s[k * 64 + r] = W[(g * 256 + ht * 16 + hh) * KCAT + k];
    }

    // GEMM thread tile: rows r0..r0+3, cols b0..b0+1
    const int rg = tid >> 4;             // 0..15
    const int bg = tid & 15;             // 0..15
    const int r0 = rg * 4;
    const int b0 = bg * 2;

    // bias pairs for rows (r0,r0+1),(r0+2,r0+3)
    const int g0  = r0 >> 4;
    const int hh0r = r0 & 15;
    float bb0 = bia[g0 * 256 + ht * 16 + hh0r + 0];
    float bb1 = bia[g0 * 256 + ht * 16 + hh0r + 1];
    float bb2 = bia[g0 * 256 + ht * 16 + hh0r + 2];
    float bb3 = bia[g0 * 256 + ht * 16 + hh0r + 3];
    const u64 bias01 = pack2(bb0, bb1);
    const u64 bias23 = pack2(bb2, bb3);

    // gate-phase cells: 2 per thread
    const int cb  = tid & 31;            // local batch
    const int hh0 = (tid >> 5) << 1;     // 0,2,...,14

    // zero c_s and h_s
    for (int idx = tid; idx < 16 * 32; idx += NTHR) c_s[idx] = 0.0f;
    for (int idx = tid; idx < 256 * 16; idx += NTHR)
        ((float4*)h_s)[idx] = make_float4(0.f, 0.f, 0.f, 0.f);

    // ---- x tile fill (duplicated cols): x_s[d][2b],[2b+1] = x[d,t,b] ----
    auto fill_x = [&](int t) {
        const float* xp = x + (size_t)t * 128 + b_base;
        for (int idx = tid; idx < 1024; idx += NTHR) {
            int d = idx >> 3, b4 = idx & 7;
            float4 v = __ldg((const float4*)(xp + (size_t)d * (S_LEN * D_DIM)) + b4);
            *(float4*)(x_s + d * 64 + b4 * 8)     = make_float4(v.x, v.x, v.y, v.y);
            *(float4*)(x_s + d * 64 + b4 * 8 + 4) = make_float4(v.z, v.z, v.w, v.w);
        }
    };

    fill_x(dir ? (S_LEN - 1) : 0);
    __syncthreads();

    u64 acc00, acc01, acc10, acc11;   // [rowpair][col]

    // ---- x-part GEMM for step 0 ----
    {
        acc00 = bias01; acc01 = bias01; acc10 = bias23; acc11 = bias23;
        const float* wp = w_s + r0;
        const float* up = x_s + b0 * 2;
#pragma unroll 8
        for (int k = 0; k < D_DIM; ++k) {
            ulonglong2 wv = *(const ulonglong2*)(wp + k * 64);
            ulonglong2 uv = *(const ulonglong2*)(up + k * 64);
            acc00 = ffma2(wv.x, uv.x, acc00);
            acc01 = ffma2(wv.x, uv.y, acc01);
            acc10 = ffma2(wv.y, uv.x, acc10);
            acc11 = ffma2(wv.y, uv.y, acc11);
        }
    }
    __syncthreads();
    if (S_LEN > 1) fill_x(dir ? (S_LEN - 2) : 1);

    for (int s = 0; s < S_LEN; ++s) {
        const int t = dir ? (S_LEN - 1 - s) : s;

        // ---- 1: wait for h(s-1) from the other 15 CTAs of the group ----
        if (tid == 0 && s > 0) {
            unsigned tgt = 16u * (unsigned)s;
            volatile unsigned* p = (volatile unsigned*)&g_bar[grp];
            while (*p < tgt) { __nanosleep(32); }
            __threadfence();
        }
        __syncthreads();

        // ---- 2: h tile fill (duplicated cols) from g_hT[(s-1)&1] ----
        if (s > 0) {
            const float* hp = &g_hT[(s - 1) & 1][dir][0][0];
            for (int idx = tid; idx < 2048; idx += NTHR) {
                int b4 = idx & 7, k = idx >> 3;
                float4 v = __ldcg((const float4*)(hp + k * 128 + b_base) + b4);
                *(float4*)(h_s + k * 64 + b4 * 8)     = make_float4(v.x, v.x, v.y, v.y);
                *(float4*)(h_s + k * 64 + b4 * 8 + 4) = make_float4(v.z, v.z, v.w, v.w);
            }
        }
        __syncthreads();

        // ---- 3: h-part GEMM (K=256) ----
        {
            const float* wp = w_s + 128 * 64 + r0;
            const float* up = h_s + b0 * 2;
#pragma unroll 8
            for (int k = 0; k < H_DIM; ++k) {
                ulonglong2 wv = *(const ulonglong2*)(wp + k * 64);
                ulonglong2 uv = *(const ulonglong2*)(up + k * 64);
                acc00 = ffma2(wv.x, uv.x, acc00);
                acc01 = ffma2(wv.x, uv.y, acc01);
                acc10 = ffma2(wv.y, uv.x, acc10);
                acc11 = ffma2(wv.y, uv.y, acc11);
            }
        }

        // ---- 4: stage z ----
        {
            float lo, hi;
            unpack2(acc00, lo, hi);
            z_s[(r0 + 0) * 32 + b0] = lo; z_s[(r0 + 1) * 32 + b0] = hi;
            unpack2(acc01, lo, hi);
            z_s[(r0 + 0) * 32 + b0 + 1] = lo; z_s[(r0 + 1) * 32 + b0 + 1] = hi;
            unpack2(acc10, lo, hi);
            z_s[(r0 + 2) * 32 + b0] = lo; z_s[(r0 + 3) * 32 + b0] = hi;
            unpack2(acc11, lo, hi);
            z_s[(r0 + 2) * 32 + b0 + 1] = lo; z_s[(r0 + 3) * 32 + b0 + 1] = hi;
        }
        __syncthreads();

        // ---- 5: gates, state update, stores ----
        {
            float hv[2], cv[2];
#pragma unroll
            for (int i = 0; i < 2; ++i) {
                int hh = hh0 + i;
                float zf = z_s[(0  + hh) * 32 + cb];
                float zi = z_s[(16 + hh) * 32 + cb];
                float zc = z_s[(32 + hh) * 32 + cb];
                float zo = z_s[(48 + hh) * 32 + cb];
                float f  = sigmoidf_fast(zf);
                float ig = sigmoidf_fast(zi);
                float ct = tanhf_fast(zc);
                float og = sigmoidf_fast(zo);
                float c  = f * c_s[hh * 32 + cb] + ig * ct;
                c_s[hh * 32 + cb] = c;
                hv[i] = og * tanhf_fast(c);
                cv[i] = c;
            }
            const int b_glob = b_base + cb;
            const int h_glob = ht * 16 + hh0;

            // transposed h state (coalesced rows of 128 b)
            g_hT[s & 1][dir][h_glob + 0][b_glob] = hv[0];
            g_hT[s & 1][dir][h_glob + 1][b_glob] = hv[1];

            // output (B, S, 2H)
            *(float2*)(out + ((size_t)b_glob * S_LEN + t) * (2 * H_DIM)
                           + dir * H_DIM + h_glob) = make_float2(hv[0], hv[1]);

            if (s == S_LEN - 1) {
                size_t base = (size_t)B_DIM * S_LEN * 2 * H_DIM;
                size_t off  = ((size_t)dir * B_DIM + b_glob) * H_DIM + h_glob;
                *(float2*)(out + base + off) = make_float2(hv[0], hv[1]);
                *(float2*)(out + base + 2u * B_DIM * H_DIM + off) =
                    make_float2(cv[0], cv[1]);
            }
        }

        // ---- 6: publish h, arrive (no wait here) ----
        __threadfence();
        __syncthreads();
        if (tid == 0) atomicAdd(&g_bar[grp], 1u);

        // ---- 7: x-part GEMM for step s+1 (independent of h) ----
        if (s + 1 < S_LEN) {
            acc00 = bias01; acc01 = bias01; acc10 = bias23; acc11 = bias23;
            const float* wp = w_s + r0;
            const float* up = x_s + b0 * 2;
#pragma unroll 8
            for (int k = 0; k < D_DIM; ++k) {
                ulonglong2 wv = *(const ulonglong2*)(wp + k * 64);
                ulonglong2 uv = *(const ulonglong2*)(up + k * 64);
                acc00 = ffma2(wv.x, uv.x, acc00);
                acc01 = ffma2(wv.x, uv.y, acc01);
                acc10 = ffma2(wv.y, uv.x, acc10);
                acc11 = ffma2(wv.y, uv.y, acc11);
            }
            __syncthreads();
            // ---- 8: prefetch x(s+2) ----
            if (s + 2 < S_LEN) fill_x(dir ? (S_LEN - 3 - s) : (s + 2));
        }
    }
}

extern "C" void kernel_launch(void* const* d_in, const int* in_sizes, int n_in,
                              void* d_out, int out_size) {
    const float* x  = (const float*)d_in[0];
    const float* Wf = (const float*)d_in[1];
    const float* bf = (const float*)d_in[2];
    const float* Wb = (const float*)d_in[3];
    const float* bb = (const float*)d_in[4];
    float* out = (float*)d_out;

    cudaFuncSetAttribute(bilstm_kernel,
                         cudaFuncAttributeMaxDynamicSharedMemorySize,
                         SMEM_BYTES);

    reset_bar_kernel<<<1, 32>>>();
    bilstm_kernel<<<128, NTHR, SMEM_BYTES>>>(x, Wf, bf, Wb, bb, out);
}

// round 4
// speedup vs baseline: 1.0413x; 1.0413x over previous
#include <cuda_runtime.h>
#include <math.h>

// BiLSTM: B=128, S=1024, D=128, H=256.
// Grid: 128 CTAs = dir(2) x btpair(4) x hslice(16, 16 h).
// Each CTA = TWO independent 128-thread halves; half hx owns batch tile
// bt = btp + 4*hx (16 batches). Halves share the smem weight tile but have
// independent named barriers + group counters, so their sync phases overlap.
// GEMM: f32x2 FFMA, w natural pairs, u duplicated pairs; 4r x 2c per thread.

#define S_LEN   1024
#define B_DIM   128
#define D_DIM   128
#define H_DIM   256
#define KCAT    384
#define NTHR    256

// smem layout (floats)
#define W_OFF   0              // w_s[384][64]
#define X_OFF   24576          // x[2][128][32]  (dup cols)
#define H_OFF   32768          // h[2][256][32]  (dup cols)
#define Z_OFF   49152          // z[2][64][20]   (padded rows)
#define SMEM_FLOATS 51712
#define SMEM_BYTES  (SMEM_FLOATS * 4)
#define ZSTRIDE 20

typedef unsigned long long u64;

__device__ float g_hT[2][2][H_DIM][B_DIM];   // [parity][dir][k][b]
__device__ unsigned int g_bar[16];           // [dir*8 + bt]

__global__ void reset_bar_kernel() {
    if (threadIdx.x < 16) g_bar[threadIdx.x] = 0u;
}

__device__ __forceinline__ u64 ffma2(u64 a, u64 b, u64 c) {
    u64 d;
    asm("fma.rn.f32x2 %0, %1, %2, %3;" : "=l"(d) : "l"(a), "l"(b), "l"(c));
    return d;
}
__device__ __forceinline__ u64 pack2(float lo, float hi) {
    u64 d;
    asm("mov.b64 %0, {%1, %2};" : "=l"(d) : "f"(lo), "f"(hi));
    return d;
}
__device__ __forceinline__ void unpack2(u64 v, float& lo, float& hi) {
    asm("mov.b64 {%0, %1}, %2;" : "=f"(lo), "=f"(hi) : "l"(v));
}
__device__ __forceinline__ void bar_half(int id) {
    asm volatile("bar.sync %0, 128;" :: "r"(id) : "memory");
}
__device__ __forceinline__ float sigmoidf_fast(float x) {
    return 1.0f / (1.0f + __expf(-x));
}
__device__ __forceinline__ float tanhf_fast(float x) {
    return 1.0f - 2.0f / (1.0f + __expf(2.0f * x));
}

__global__ void __launch_bounds__(NTHR, 1)
bilstm_kernel(const float* __restrict__ x,
              const float* __restrict__ Wf, const float* __restrict__ bf,
              const float* __restrict__ Wb, const float* __restrict__ bb,
              float* __restrict__ out)
{
    extern __shared__ float smem[];
    float* w_s = smem + W_OFF;

    const int tid = threadIdx.x;
    const int cta = blockIdx.x;          // 0..127
    const int dir = cta >> 6;
    const int btp = (cta >> 4) & 3;
    const int ht  = cta & 15;

    const int hx   = tid >> 7;           // half index
    const int ltid = tid & 127;
    const int bt   = btp + 4 * hx;       // 0..7
    const int grp  = dir * 8 + bt;
    const int barid = 1 + hx;
    const int b_base = bt * 16;

    float* xs = smem + X_OFF + hx * (128 * 32);
    float* hs = smem + H_OFF + hx * (256 * 32);
    float* zs = smem + Z_OFF + hx * (64 * ZSTRIDE);

    const float* W   = dir ? Wb : Wf;    // (4,256,384)
    const float* bia = dir ? bb : bf;

    // ---- weights (shared by both halves): w_s[k][r], r = g*16+hh ----
    for (int idx = tid; idx < KCAT * 64; idx += NTHR) {
        int k = idx % KCAT;
        int r = idx / KCAT;
        int g = r >> 4, hh = r & 15;
        w_s[k * 64 + r] = W[(g * 256 + ht * 16 + hh) * KCAT + k];
    }

    // GEMM thread tile: rows r0..r0+3 (pairs), cols b0,b0+1 (dup)
    const int rg = ltid >> 3;            // 0..15
    const int cg = ltid & 7;             // 0..7
    const int r0 = rg * 4;
    const int b0 = cg * 2;

    const int g0   = r0 >> 4;
    const int hh0r = r0 & 15;
    const u64 bias01 = pack2(bia[g0 * 256 + ht * 16 + hh0r + 0],
                             bia[g0 * 256 + ht * 16 + hh0r + 1]);
    const u64 bias23 = pack2(bia[g0 * 256 + ht * 16 + hh0r + 2],
                             bia[g0 * 256 + ht * 16 + hh0r + 3]);

    // gate cells: fixed per thread -> c state in registers
    const int cb  = ltid & 15;           // local batch 0..15
    const int hh0 = (ltid >> 4) << 1;    // 0,2,...,14
    float c0 = 0.0f, c1 = 0.0f;

    // zero h tile (s = 0 initial state)
    for (int i = ltid; i < 2048; i += 128)
        ((float4*)hs)[i] = make_float4(0.f, 0.f, 0.f, 0.f);

    // x tile fill (dup cols): xs[d][2b],[2b+1] = x[d, t, b_base+b]
    auto fill_x = [&](int t) {
        const float* xp = x + (size_t)t * 128 + b_base;
        for (int i = ltid; i < 512; i += 128) {
            int d = i >> 2, b4 = i & 3;
            float4 v = __ldg((const float4*)(xp + (size_t)d * (S_LEN * D_DIM)) + b4);
            *(float4*)(xs + d * 32 + b4 * 8)     = make_float4(v.x, v.x, v.y, v.y);
            *(float4*)(xs + d * 32 + b4 * 8 + 4) = make_float4(v.z, v.z, v.w, v.w);
        }
    };

    fill_x(dir ? (S_LEN - 1) : 0);
    __syncthreads();   // weights + tiles ready

    u64 acc00, acc01, acc10, acc11;

    // x-part GEMM for step 0
    {
        acc00 = bias01; acc01 = bias01; acc10 = bias23; acc11 = bias23;
        const float* wp = w_s + r0;
        const float* up = xs + b0 * 2;
#pragma unroll 8
        for (int k = 0; k < D_DIM; ++k) {
            ulonglong2 wv = *(const ulonglong2*)(wp + k * 64);
            ulonglong2 uv = *(const ulonglong2*)(up + k * 32);
            acc00 = ffma2(wv.x, uv.x, acc00);
            acc01 = ffma2(wv.x, uv.y, acc01);
            acc10 = ffma2(wv.y, uv.x, acc10);
            acc11 = ffma2(wv.y, uv.y, acc11);
        }
    }
    bar_half(barid);
    if (S_LEN > 1) fill_x(dir ? (S_LEN - 2) : 1);

    for (int s = 0; s < S_LEN; ++s) {
        const int t = dir ? (S_LEN - 1 - s) : s;

        // 1: wait for h(s-1) from the 16 CTAs of this (dir, bt) group
        if (ltid == 0 && s > 0) {
            unsigned tgt = 16u * (unsigned)s;
            volatile unsigned* p = (volatile unsigned*)&g_bar[grp];
            while (*p < tgt) {}
            __threadfence();
        }
        bar_half(barid);

        // 2: h tile fill (dup cols) from g_hT[(s-1)&1]
        if (s > 0) {
            const float* hp = &g_hT[(s - 1) & 1][dir][0][b_base];
            for (int i = ltid; i < 1024; i += 128) {
                int k = i >> 2, b4 = i & 3;
                float4 v = __ldcg((const float4*)(hp + (size_t)k * 128) + b4);
                *(float4*)(hs + k * 32 + b4 * 8)     = make_float4(v.x, v.x, v.y, v.y);
                *(float4*)(hs + k * 32 + b4 * 8 + 4) = make_float4(v.z, v.z, v.w, v.w);
            }
        }
        bar_half(barid);

        // 3: h-part GEMM (K=256)
        {
            const float* wp = w_s + 128 * 64 + r0;
            const float* up = hs + b0 * 2;
#pragma unroll 8
            for (int k = 0; k < H_DIM; ++k) {
                ulonglong2 wv = *(const ulonglong2*)(wp + k * 64);
                ulonglong2 uv = *(const ulonglong2*)(up + k * 32);
                acc00 = ffma2(wv.x, uv.x, acc00);
                acc01 = ffma2(wv.x, uv.y, acc01);
                acc10 = ffma2(wv.y, uv.x, acc10);
                acc11 = ffma2(wv.y, uv.y, acc11);
            }
        }

        // 4: stage z
        {
            float lo, hi;
            unpack2(acc00, lo, hi);
            zs[(r0 + 0) * ZSTRIDE + b0] = lo; zs[(r0 + 1) * ZSTRIDE + b0] = hi;
            unpack2(acc01, lo, hi);
            zs[(r0 + 0) * ZSTRIDE + b0 + 1] = lo; zs[(r0 + 1) * ZSTRIDE + b0 + 1] = hi;
            unpack2(acc10, lo, hi);
            zs[(r0 + 2) * ZSTRIDE + b0] = lo; zs[(r0 + 3) * ZSTRIDE + b0] = hi;
            unpack2(acc11, lo, hi);
            zs[(r0 + 2) * ZSTRIDE + b0 + 1] = lo; zs[(r0 + 3) * ZSTRIDE + b0 + 1] = hi;
        }
        bar_half(barid);

        // 5: gates, c update (registers), h/out stores
        {
            float hv0, hv1;
            {
                int hh = hh0;
                float f  = sigmoidf_fast(zs[(0  + hh) * ZSTRIDE + cb]);
                float ig = sigmoidf_fast(zs[(16 + hh) * ZSTRIDE + cb]);
                float ct = tanhf_fast  (zs[(32 + hh) * ZSTRIDE + cb]);
                float og = sigmoidf_fast(zs[(48 + hh) * ZSTRIDE + cb]);
                c0 = f * c0 + ig * ct;
                hv0 = og * tanhf_fast(c0);
            }
            {
                int hh = hh0 + 1;
                float f  = sigmoidf_fast(zs[(0  + hh) * ZSTRIDE + cb]);
                float ig = sigmoidf_fast(zs[(16 + hh) * ZSTRIDE + cb]);
                float ct = tanhf_fast  (zs[(32 + hh) * ZSTRIDE + cb]);
                float og = sigmoidf_fast(zs[(48 + hh) * ZSTRIDE + cb]);
                c1 = f * c1 + ig * ct;
                hv1 = og * tanhf_fast(c1);
            }
            const int b_glob = b_base + cb;
            const int h_glob = ht * 16 + hh0;

            g_hT[s & 1][dir][h_glob + 0][b_glob] = hv0;
            g_hT[s & 1][dir][h_glob + 1][b_glob] = hv1;

            *(float2*)(out + ((size_t)b_glob * S_LEN + t) * (2 * H_DIM)
                           + dir * H_DIM + h_glob) = make_float2(hv0, hv1);

            if (s == S_LEN - 1) {
                size_t base = (size_t)B_DIM * S_LEN * 2 * H_DIM;
                size_t off  = ((size_t)dir * B_DIM + b_glob) * H_DIM + h_glob;
                *(float2*)(out + base + off) = make_float2(hv0, hv1);
                *(float2*)(out + base + 2u * B_DIM * H_DIM + off) =
                    make_float2(c0, c1);
            }
        }

        // 6: publish h(s), arrive
        bar_half(barid);
        if (ltid == 0) {
            __threadfence();
            atomicAdd(&g_bar[grp], 1u);
        }

        // 7: x-part GEMM for step s+1, then prefetch x(s+2)
        if (s + 1 < S_LEN) {
            acc00 = bias01; acc01 = bias01; acc10 = bias23; acc11 = bias23;
            const float* wp = w_s + r0;
            const float* up = xs + b0 * 2;
#pragma unroll 8
            for (int k = 0; k < D_DIM; ++k) {
                ulonglong2 wv = *(const ulonglong2*)(wp + k * 64);
                ulonglong2 uv = *(const ulonglong2*)(up + k * 32);
                acc00 = ffma2(wv.x, uv.x, acc00);
                acc01 = ffma2(wv.x, uv.y, acc01);
                acc10 = ffma2(wv.y, uv.x, acc10);
                acc11 = ffma2(wv.y, uv.y, acc11);
            }
            bar_half(barid);
            if (s + 2 < S_LEN) fill_x(dir ? (S_LEN - 3 - s) : (s + 2));
        }
    }
}

extern "C" void kernel_launch(void* const* d_in, const int* in_sizes, int n_in,
                              void* d_out, int out_size) {
    const float* x  = (const float*)d_in[0];
    const float* Wf = (const float*)d_in[1];
    const float* bf = (const float*)d_in[2];
    const float* Wb = (const float*)d_in[3];
    const float* bb = (const float*)d_in[4];
    float* out = (float*)d_out;

    cudaFuncSetAttribute(bilstm_kernel,
                         cudaFuncAttributeMaxDynamicSharedMemorySize,
                         SMEM_BYTES);

    reset_bar_kernel<<<1, 32>>>();
    bilstm_kernel<<<128, NTHR, SMEM_BYTES>>>(x, Wf, bf, Wb, bb, out);
}

// round 6
// speedup vs baseline: 2.0463x; 1.9652x over previous
#include <cuda_runtime.h>
#include <cuda_bf16.h>
#include <stdint.h>

// BiLSTM B=128,S=1024,D=128,H=256 — bf16 3-split GEMM via mma.sync (HMMA).
// 128 CTAs = dir(2) x rowslice(8, M=128 = 4 gates x 32 h) x btile(8, N=16).
// A (weights) resident in smem, bf16 hi/lo, ldmatrix-tile-packed.
// u = [x;h] in smem as [k=384][n=16] bf16 hi/lo (coalesced fills).
// z = Whi*uhi + Whi*ulo + Wlo*uhi, fp32 register accumulators.
// x-part GEMM (kt0-7) issued before the 8-CTA group barrier; h-part after.

#define S_LEN 1024
#define NTHR  256

#define A_HI_OFF 0          // 8mt x 24kt x 512B = 98304
#define A_LO_OFF 98304
#define B_HI_OFF 196608     // [384][16] bf16, 32B rows = 12288
#define B_LO_OFF 208896
#define Z_OFF    221184     // float z[128][18] = 9216
#define SMEM_BYTES 230400

__device__ float g_hT[2][2][8][256][16];   // [parity][dir][btl][k][b]
__device__ unsigned g_barrier[16];

__global__ void reset_bar_kernel() {
    if (threadIdx.x < 16) g_barrier[threadIdx.x] = 0u;
}

__device__ __forceinline__ uint32_t smem_u32(const void* p) {
    uint32_t a;
    asm("{ .reg .u64 t; cvta.to.shared.u64 t, %1; cvt.u32.u64 %0, t; }"
        : "=r"(a) : "l"(p));
    return a;
}
__device__ __forceinline__ void ldsm4(uint32_t* r, uint32_t a) {
    asm volatile("ldmatrix.sync.aligned.m8n8.x4.shared.b16 {%0,%1,%2,%3}, [%4];"
                 : "=r"(r[0]), "=r"(r[1]), "=r"(r[2]), "=r"(r[3]) : "r"(a));
}
__device__ __forceinline__ void ldsm4t(uint32_t* r, uint32_t a) {
    asm volatile("ldmatrix.sync.aligned.m8n8.x4.trans.shared.b16 {%0,%1,%2,%3}, [%4];"
                 : "=r"(r[0]), "=r"(r[1]), "=r"(r[2]), "=r"(r[3]) : "r"(a));
}
__device__ __forceinline__ void mma16816(float* d, const uint32_t* a, const uint32_t* b) {
    asm volatile(
        "mma.sync.aligned.m16n8k16.row.col.f32.bf16.bf16.f32 "
        "{%0,%1,%2,%3}, {%4,%5,%6,%7}, {%8,%9}, {%0,%1,%2,%3};"
        : "+f"(d[0]), "+f"(d[1]), "+f"(d[2]), "+f"(d[3])
        : "r"(a[0]), "r"(a[1]), "r"(a[2]), "r"(a[3]), "r"(b[0]), "r"(b[1]));
}

__device__ __forceinline__ uint2 split_pack4(float4 v, uint2& lo_out) {
    __nv_bfloat16 h0 = __float2bfloat16_rn(v.x), h1 = __float2bfloat16_rn(v.y);
    __nv_bfloat16 h2 = __float2bfloat16_rn(v.z), h3 = __float2bfloat16_rn(v.w);
    __nv_bfloat16 l0 = __float2bfloat16_rn(v.x - __bfloat162float(h0));
    __nv_bfloat16 l1 = __float2bfloat16_rn(v.y - __bfloat162float(h1));
    __nv_bfloat16 l2 = __float2bfloat16_rn(v.z - __bfloat162float(h2));
    __nv_bfloat16 l3 = __float2bfloat16_rn(v.w - __bfloat162float(h3));
    uint2 hi;
    hi.x = ((uint32_t)__bfloat16_as_ushort(h1) << 16) | __bfloat16_as_ushort(h0);
    hi.y = ((uint32_t)__bfloat16_as_ushort(h3) << 16) | __bfloat16_as_ushort(h2);
    lo_out.x = ((uint32_t)__bfloat16_as_ushort(l1) << 16) | __bfloat16_as_ushort(l0);
    lo_out.y = ((uint32_t)__bfloat16_as_ushort(l3) << 16) | __bfloat16_as_ushort(l2);
    return hi;
}

__device__ __forceinline__ float sigmoidf_fast(float x) {
    return 1.0f / (1.0f + __expf(-x));
}
__device__ __forceinline__ float tanhf_fast(float x) {
    return 1.0f - 2.0f / (1.0f + __expf(2.0f * x));
}

__global__ void __launch_bounds__(NTHR, 1)
bilstm_mma_kernel(const float* __restrict__ x,
                  const float* __restrict__ Wf, const float* __restrict__ bf,
                  const float* __restrict__ Wb, const float* __restrict__ bb,
                  float* __restrict__ out)
{
    extern __shared__ char smem[];
    const uint32_t sb = smem_u32(smem);
    const int tid  = threadIdx.x;
    const int wid  = tid >> 5;
    const int lane = tid & 31;

    const int dir = blockIdx.x >> 6;
    const int rs  = (blockIdx.x >> 3) & 7;
    const int btl = blockIdx.x & 7;
    const int grp = dir * 8 + btl;
    const int b_base = btl * 16;

    const float* W   = dir ? Wb : Wf;    // (4,256,384)
    const float* bia = dir ? bb : bf;
    float* z_s = (float*)(smem + Z_OFF);

    // ---- A: weights -> bf16 hi/lo ldmatrix tiles ----
    // tile(mt,kt) 512B: sub = ((k>>3)&1)*2 + ((r>>3)&1); 16B rows of 8 k.
    for (int idx = tid; idx < 128 * 96; idx += NTHR) {
        int r = idx / 96, j = idx % 96, k0 = j * 4;
        int wr = (r >> 5) * 256 + rs * 32 + (r & 31);
        float4 v = *(const float4*)(W + (size_t)wr * 384 + k0);
        uint2 lo, hi = split_pack4(v, lo);
        uint32_t byte = (uint32_t)(((r >> 4) * 24 + (k0 >> 4)) * 512
                       + (((k0 >> 3) & 1) * 2 + ((r >> 3) & 1)) * 128
                       + (r & 7) * 16 + (k0 & 7) * 2);
        *(uint2*)(smem + A_HI_OFF + byte) = hi;
        *(uint2*)(smem + A_LO_OFF + byte) = lo;
    }

    // per-thread bias for accum rows
    const int r1 = wid * 16 + (lane >> 2);
    const int r2 = r1 + 8;
    const float bv1 = bia[(r1 >> 5) * 256 + rs * 32 + (r1 & 31)];
    const float bv2 = bia[(r2 >> 5) * 256 + rs * 32 + (r2 & 31)];

    // zero u h-region (rows 128..383) for s=0
    for (int i = tid; i < 512; i += NTHR) {
        ((uint4*)(smem + B_HI_OFF + 4096))[i] = make_uint4(0, 0, 0, 0);
        ((uint4*)(smem + B_LO_OFF + 4096))[i] = make_uint4(0, 0, 0, 0);
    }

    // x fill: u[k][n] rows 0..127
    auto fill_x = [&](int tt) {
        for (int i = tid; i < 512; i += NTHR) {
            int k = i >> 2, j = i & 3;
            float4 v = __ldg((const float4*)(x + (size_t)k * (S_LEN * 128)
                                               + (size_t)tt * 128 + b_base + j * 4));
            uint2 lo, hi = split_pack4(v, lo);
            *(uint2*)(smem + B_HI_OFF + k * 32 + j * 8) = hi;
            *(uint2*)(smem + B_LO_OFF + k * 32 + j * 8) = lo;
        }
    };
    fill_x(dir ? (S_LEN - 1) : 0);
    __syncthreads();

    // per-thread ldmatrix base addresses
    const uint32_t aHi0 = sb + A_HI_OFF + (uint32_t)(wid * 24 * 512)
                        + ((lane >> 3) * 128) + ((lane & 7) * 16);
    const int sub = lane >> 3;
    const int kk  = (lane & 7) + (sub & 1) * 8;
    const int nb  = sub >> 1;
    const uint32_t bHi0 = sb + B_HI_OFF + (uint32_t)(kk * 32 + nb * 16);

    // gate cells
    const int cb  = tid & 15;
    const int hh0 = (tid >> 4) << 1;
    float c0 = 0.0f, c1 = 0.0f;
    const int n0 = (lane & 3) * 2;

    for (int s = 0; s < S_LEN; ++s) {
        const int t = dir ? (S_LEN - 1 - s) : s;

        float acc0[4] = {0.f, 0.f, 0.f, 0.f};
        float acc1[4] = {0.f, 0.f, 0.f, 0.f};

        uint32_t aH = aHi0, bH = bHi0;

        // ---- x-part GEMM: kt 0..7 (independent of h(s-1)) ----
#pragma unroll
        for (int kt = 0; kt < 8; ++kt) {
            uint32_t ah[4], al[4], bh[4], bl[4];
            ldsm4 (ah, aH);
            ldsm4 (al, aH + 98304u);
            ldsm4t(bh, bH);
            ldsm4t(bl, bH + 12288u);
            mma16816(acc0, ah, bh);     mma16816(acc1, ah, bh + 2);
            mma16816(acc0, ah, bl);     mma16816(acc1, ah, bl + 2);
            mma16816(acc0, al, bh);     mma16816(acc1, al, bh + 2);
            aH += 512u; bH += 512u;
        }

        // ---- group barrier + h fill ----
        if (s > 0) {
            if (tid == 0) {
                unsigned tgt = 8u * (unsigned)s;
                volatile unsigned* p = (volatile unsigned*)&g_barrier[grp];
                while (*p < tgt) {}
                __threadfence();
            }
            __syncthreads();
            const float* hp = &g_hT[(s - 1) & 1][dir][btl][0][0];
            for (int i = tid; i < 1024; i += NTHR) {
                int k = i >> 2, j = i & 3;
                float4 v = *(const float4*)(hp + k * 16 + j * 4);
                uint2 lo, hi = split_pack4(v, lo);
                *(uint2*)(smem + B_HI_OFF + (128 + k) * 32 + j * 8) = hi;
                *(uint2*)(smem + B_LO_OFF + (128 + k) * 32 + j * 8) = lo;
            }
            __syncthreads();
        }

        // ---- h-part GEMM: kt 8..23 ----
#pragma unroll
        for (int kt = 0; kt < 16; ++kt) {
            uint32_t ah[4], al[4], bh[4], bl[4];
            ldsm4 (ah, aH);
            ldsm4 (al, aH + 98304u);
            ldsm4t(bh, bH);
            ldsm4t(bl, bH + 12288u);
            mma16816(acc0, ah, bh);     mma16816(acc1, ah, bh + 2);
            mma16816(acc0, ah, bl);     mma16816(acc1, ah, bl + 2);
            mma16816(acc0, al, bh);     mma16816(acc1, al, bh + 2);
            aH += 512u; bH += 512u;
        }

        // ---- stage z (+bias) ----
        *(float2*)(z_s + r1 * 18 + n0)     = make_float2(acc0[0] + bv1, acc0[1] + bv1);
        *(float2*)(z_s + r2 * 18 + n0)     = make_float2(acc0[2] + bv2, acc0[3] + bv2);
        *(float2*)(z_s + r1 * 18 + n0 + 8) = make_float2(acc1[0] + bv1, acc1[1] + bv1);
        *(float2*)(z_s + r2 * 18 + n0 + 8) = make_float2(acc1[2] + bv2, acc1[3] + bv2);
        __syncthreads();

        // ---- gates ----
        float hv0, hv1;
        {
            int hh = hh0;
            float f  = sigmoidf_fast(z_s[(0  + hh) * 18 + cb]);
            float ig = sigmoidf_fast(z_s[(32 + hh) * 18 + cb]);
            float ct = tanhf_fast  (z_s[(64 + hh) * 18 + cb]);
            float og = sigmoidf_fast(z_s[(96 + hh) * 18 + cb]);
            c0 = f * c0 + ig * ct;
            hv0 = og * tanhf_fast(c0);
        }
        {
            int hh = hh0 + 1;
            float f  = sigmoidf_fast(z_s[(0  + hh) * 18 + cb]);
            float ig = sigmoidf_fast(z_s[(32 + hh) * 18 + cb]);
            float ct = tanhf_fast  (z_s[(64 + hh) * 18 + cb]);
            float og = sigmoidf_fast(z_s[(96 + hh) * 18 + cb]);
            c1 = f * c1 + ig * ct;
            hv1 = og * tanhf_fast(c1);
        }
        const int b_glob = b_base + cb;
        const int h_glob = rs * 32 + hh0;

        g_hT[s & 1][dir][btl][h_glob + 0][cb] = hv0;
        g_hT[s & 1][dir][btl][h_glob + 1][cb] = hv1;

        *(float2*)(out + ((size_t)b_glob * S_LEN + t) * 512 + dir * 256 + h_glob)
            = make_float2(hv0, hv1);
        if (s == S_LEN - 1) {
            size_t base = (size_t)128 * S_LEN * 512;
            size_t off  = ((size_t)dir * 128 + b_glob) * 256 + h_glob;
            *(float2*)(out + base + off) = make_float2(hv0, hv1);
            *(float2*)(out + base + 2u * 128 * 256 + off) = make_float2(c0, c1);
        }

        // ---- publish + arrive ----
        __threadfence();
        __syncthreads();
        if (tid == 0) atomicAdd(&g_barrier[grp], 1u);

        // ---- x fill for s+1 ----
        if (s + 1 < S_LEN) fill_x(dir ? (S_LEN - 2 - s) : (s + 1));
        __syncthreads();
    }
}

extern "C" void kernel_launch(void* const* d_in, const int* in_sizes, int n_in,
                              void* d_out, int out_size) {
    const float* x  = (const float*)d_in[0];
    const float* Wf = (const float*)d_in[1];
    const float* bf = (const float*)d_in[2];
    const float* Wb = (const float*)d_in[3];
    const float* bb = (const float*)d_in[4];
    float* out = (float*)d_out;

    cudaFuncSetAttribute(bilstm_mma_kernel,
                         cudaFuncAttributeMaxDynamicSharedMemorySize,
                         SMEM_BYTES);

    reset_bar_kernel<<<1, 32>>>();
    bilstm_mma_kernel<<<128, NTHR, SMEM_BYTES>>>(x, Wf, bf, Wb, bb, out);
}